// round 16
// baseline (speedup 1.0000x reference)
#include <cuda_runtime.h>
#include <cuda_fp16.h>
#include <cstdint>

#define MAX_N   131072
#define MAX_E   1700000
#define D       128
#define SCAN_B  512
#define MAX_BLK 256   // MAX_N / SCAN_B

#define A_STRIDE 136
#define W_STRIDE 136
#define GEMM_SMEM_BYTES ((128 * A_STRIDE + 128 * W_STRIDE) * 2)

// lookback status flags (bits 31:30): 01 = aggregate, 10 = inclusive prefix
#define FLAG_AGG  (1u << 30)
#define FLAG_PFX  (2u << 30)
#define VAL_MASK  0x3FFFFFFFu

// ---- scratch (__device__ globals; no allocations allowed) ----
__device__ __align__(16) __half2 g_bufh[(size_t)MAX_N * 64];  // g = dinv*relu(LN(x))@W, fp16
__device__ __align__(16) __half2 g_Wh2[64 * 128];             // W in fp16, row-major [k][n]
__device__ float g_dinv[MAX_N];
__device__ int   g_cnt[MAX_N];
__device__ int   g_rowptr[MAX_N + 1];
__device__ int   g_cur[MAX_N];
__device__ unsigned g_stat[MAX_BLK];   // lookback status
__device__ int   g_src[MAX_E];
__device__ int   g_e64;

// ---------------------------------------------------------------------------
__device__ __forceinline__ unsigned h2_as_u32(__half2 h) {
    union { __half2 h; unsigned u; } cvt; cvt.h = h; return cvt.u;
}
__device__ __forceinline__ __half2 u32_as_h2(unsigned u) {
    union { unsigned u; __half2 h; } cvt; cvt.u = u; return cvt.h;
}
__device__ __forceinline__ uint32_t smem_u32(const void* p) {
    return (uint32_t)__cvta_generic_to_shared(p);
}

// ---------------------------------------------------------------------------
// k_init: zero g_cnt + dtype probe (block 0) + W->fp16 (blocks 1..32)
//         + zero lookback status (block 33).
__global__ void k_init(const void* __restrict__ edges, const float* __restrict__ W,
                       int N, int n) {
    __shared__ int bad;
    const int i = blockIdx.x * blockDim.x + threadIdx.x;
    if (i < n) g_cnt[i] = 0;
    if (blockIdx.x == 0) {
        if (threadIdx.x == 0) bad = 0;
        __syncthreads();
        if (threadIdx.x < 64) {
            long long v = ((const long long*)edges)[threadIdx.x];
            if (v < 0 || v >= (long long)N) atomicOr(&bad, 1);
        }
        __syncthreads();
        if (threadIdx.x == 0) g_e64 = bad ? 0 : 1;
    } else if (blockIdx.x <= 32) {
        const int j = (blockIdx.x - 1) * 256 + threadIdx.x;  // [0, 8192)
        const float2 w = ((const float2*)W)[j];
        g_Wh2[j] = __floats2half2_rn(w.x, w.y);
    } else if (blockIdx.x == 33) {
        if (threadIdx.x < MAX_BLK) g_stat[threadIdx.x] = 0;
    }
}

// histogram over edge targets, 4 edges/thread (vector fast path when E%4==0).
__global__ void k_hist(const void* __restrict__ edges, int E, int N) {
    const int t  = blockIdx.x * blockDim.x + threadIdx.x;
    const int e0 = t * 4;
    if (e0 >= E) return;
    const int e64 = g_e64;
    int c[4];
    int cnt;
    if (e0 + 4 <= E && ((E & 3) == 0)) {
        if (e64) {
            const longlong2* p = (const longlong2*)((const long long*)edges + (long long)E + e0);
            const longlong2 v0 = p[0];
            const longlong2 v1 = p[1];
            c[0] = (int)v0.x; c[1] = (int)v0.y; c[2] = (int)v1.x; c[3] = (int)v1.y;
        } else {
            const int4 v = *(const int4*)((const int*)edges + (long long)E + e0);
            c[0] = v.x; c[1] = v.y; c[2] = v.z; c[3] = v.w;
        }
        cnt = 4;
    } else {
        cnt = E - e0; if (cnt > 4) cnt = 4;
        for (int j = 0; j < cnt; j++)
            c[j] = e64 ? (int)((const long long*)edges)[(long long)E + e0 + j]
                       : ((const int*)edges)[(long long)E + e0 + j];
    }
    #pragma unroll
    for (int j = 0; j < 4; j++)
        if (j < cnt && (unsigned)c[j] < (unsigned)N) atomicAdd(&g_cnt[c[j]], 1);
}

// Fused scan (scan1+scan3): decoupled-lookback exclusive scan of g_cnt ->
// g_rowptr/g_cur, plus dinv. All nblk (<=196) blocks co-resident -> safe.
__global__ void __launch_bounds__(SCAN_B) k_scan(int n, int E) {
    __shared__ int s[SCAN_B];
    __shared__ int excl_base;
    const int bid = blockIdx.x;
    const int tid = threadIdx.x;
    const int i   = bid * SCAN_B + tid;
    const int v   = (i < n) ? g_cnt[i] : 0;
    if (i < n) g_dinv[i] = rsqrtf((float)(v + 1));   // +1 self loop
    s[tid] = v;
    __syncthreads();
    #pragma unroll
    for (int off = 1; off < SCAN_B; off <<= 1) {
        int t = (tid >= off) ? s[tid - off] : 0;
        __syncthreads();
        s[tid] += t;
        __syncthreads();
    }
    const int incl = s[tid];
    const unsigned agg = (unsigned)s[SCAN_B - 1];

    if (tid == 0) {
        volatile unsigned* stat = (volatile unsigned*)g_stat;
        if (bid == 0) {
            stat[0] = FLAG_PFX | agg;
            excl_base = 0;
        } else {
            stat[bid] = FLAG_AGG | agg;
            unsigned sum = 0;
            int look = bid - 1;
            while (true) {
                unsigned st;
                do { st = stat[look]; } while (st == 0);
                sum += st & VAL_MASK;
                if (st & FLAG_PFX) break;
                look--;
            }
            excl_base = (int)sum;
            stat[bid] = FLAG_PFX | (sum + agg);
        }
    }
    __syncthreads();
    const int excl = excl_base + incl - v;
    if (i < n) { g_rowptr[i] = excl; g_cur[i] = excl; }
    if (bid == 0 && tid == 0) g_rowptr[n] = E;
}

// ---------------------------------------------------------------------------
// Fused LayerNorm -> ReLU -> HMMA GEMM -> *rsqrt(cnt+1), fp16 out.
// Stream-1 branch; depends only on k_init (W) + k_hist (g_cnt).
__global__ void __launch_bounds__(512) fused_ln_gemm_kernel(
    const float* __restrict__ x,
    const float* __restrict__ gamma,
    const float* __restrict__ beta,
    int N)
{
    extern __shared__ __align__(16) __half smem[];
    __half* A_s = smem;                     // [128][A_STRIDE]
    __half* W_s = smem + 128 * A_STRIDE;    // [128][W_STRIDE]

    const int tid  = threadIdx.x;
    const int warp = tid >> 5;
    const int lane = tid & 31;
    const int node0 = blockIdx.x * 128;

    {
        const uint4* src = (const uint4*)g_Wh2;
        #pragma unroll
        for (int i = tid; i < 2048; i += 512) {
            const int row = i >> 4;
            const int c8  = i & 15;
            *(uint4*)&W_s[row * W_STRIDE + c8 * 8] = src[i];
        }
    }

    #pragma unroll
    for (int rr = 0; rr < 8; rr++) {
        const int n = warp * 8 + rr;
        const int node = node0 + n;
        float v0 = 0.f, v1 = 0.f, v2 = 0.f, v3 = 0.f;
        if (node < N) {
            const float* xr = x + (size_t)node * D;
            v0 = xr[lane]; v1 = xr[lane + 32]; v2 = xr[lane + 64]; v3 = xr[lane + 96];
        }
        float s  = v0 + v1 + v2 + v3;
        float sq = v0 * v0 + v1 * v1 + v2 * v2 + v3 * v3;
        #pragma unroll
        for (int off = 16; off; off >>= 1) {
            s  += __shfl_xor_sync(0xFFFFFFFFu, s,  off);
            sq += __shfl_xor_sync(0xFFFFFFFFu, sq, off);
        }
        const float mu  = s * (1.0f / 128.0f);
        const float var = sq * (1.0f / 128.0f) - mu * mu;
        const float rs  = rsqrtf(var + 1e-5f);
        __half* ar = &A_s[n * A_STRIDE];
        ar[lane]      = __float2half(fmaxf((v0 - mu) * rs * gamma[lane]      + beta[lane],      0.f));
        ar[lane + 32] = __float2half(fmaxf((v1 - mu) * rs * gamma[lane + 32] + beta[lane + 32], 0.f));
        ar[lane + 64] = __float2half(fmaxf((v2 - mu) * rs * gamma[lane + 64] + beta[lane + 64], 0.f));
        ar[lane + 96] = __float2half(fmaxf((v3 - mu) * rs * gamma[lane + 96] + beta[lane + 96], 0.f));
    }
    __syncthreads();

    const int wm = warp >> 2;
    const int wn = warp & 3;

    float acc[2][4][4];
    #pragma unroll
    for (int mt = 0; mt < 2; mt++)
        #pragma unroll
        for (int nn = 0; nn < 4; nn++)
            #pragma unroll
            for (int c = 0; c < 4; c++) acc[mt][nn][c] = 0.f;

    const uint32_t a_addr0 = smem_u32(&A_s[(wm * 32 + (lane & 15)) * A_STRIDE + (lane >> 4) * 8]);
    const uint32_t a_addr1 = a_addr0 + 16 * A_STRIDE * 2;
    const uint32_t b_addr0 = smem_u32(&W_s[(lane & 15) * W_STRIDE + wn * 32]);

    #pragma unroll
    for (int kk = 0; kk < 8; kk++) {
        uint32_t b0[4], b1[4];
        const uint32_t b_k = b_addr0 + kk * (16 * W_STRIDE * 2);
        #pragma unroll
        for (int nn = 0; nn < 4; nn++) {
            asm volatile("ldmatrix.sync.aligned.m8n8.x2.trans.shared.b16 {%0,%1}, [%2];"
                         : "=r"(b0[nn]), "=r"(b1[nn])
                         : "r"(b_k + nn * 16));
        }
        uint32_t a[2][4];
        asm volatile("ldmatrix.sync.aligned.m8n8.x4.shared.b16 {%0,%1,%2,%3}, [%4];"
                     : "=r"(a[0][0]), "=r"(a[0][1]), "=r"(a[0][2]), "=r"(a[0][3])
                     : "r"(a_addr0 + kk * 32));
        asm volatile("ldmatrix.sync.aligned.m8n8.x4.shared.b16 {%0,%1,%2,%3}, [%4];"
                     : "=r"(a[1][0]), "=r"(a[1][1]), "=r"(a[1][2]), "=r"(a[1][3])
                     : "r"(a_addr1 + kk * 32));
        #pragma unroll
        for (int mt = 0; mt < 2; mt++)
            #pragma unroll
            for (int nn = 0; nn < 4; nn++)
                asm volatile("mma.sync.aligned.m16n8k16.row.col.f32.f16.f16.f32 "
                             "{%0,%1,%2,%3}, {%4,%5,%6,%7}, {%8,%9}, {%0,%1,%2,%3};"
                             : "+f"(acc[mt][nn][0]), "+f"(acc[mt][nn][1]),
                               "+f"(acc[mt][nn][2]), "+f"(acc[mt][nn][3])
                             : "r"(a[mt][0]), "r"(a[mt][1]), "r"(a[mt][2]), "r"(a[mt][3]),
                               "r"(b0[nn]), "r"(b1[nn]));
    }

    const int group = lane >> 2;
    const int qp    = lane & 3;
    #pragma unroll
    for (int mt = 0; mt < 2; mt++) {
        const int r0 = node0 + wm * 32 + mt * 16 + group;
        const int r1 = r0 + 8;
        const float dv0 = (r0 < N) ? rsqrtf((float)(g_cnt[r0] + 1)) : 0.f;
        const float dv1 = (r1 < N) ? rsqrtf((float)(g_cnt[r1] + 1)) : 0.f;
        #pragma unroll
        for (int nn = 0; nn < 4; nn++) {
            const int col2 = wn * 16 + nn * 4 + qp;
            if (r0 < N)
                g_bufh[(size_t)r0 * 64 + col2] =
                    __floats2half2_rn(acc[mt][nn][0] * dv0, acc[mt][nn][1] * dv0);
            if (r1 < N)
                g_bufh[(size_t)r1 * 64 + col2] =
                    __floats2half2_rn(acc[mt][nn][2] * dv1, acc[mt][nn][3] * dv1);
        }
    }
}

// ---------------------------------------------------------------------------
// CSR fill, 4 edges/thread.
__global__ void k_fill(const void* __restrict__ edges, int E, int N) {
    const int t  = blockIdx.x * blockDim.x + threadIdx.x;
    const int e0 = t * 4;
    if (e0 >= E) return;
    const int e64 = g_e64;
    int r[4], c[4];
    int cnt;
    if (e0 + 4 <= E && ((E & 3) == 0)) {
        if (e64) {
            const longlong2* pr = (const longlong2*)((const long long*)edges + e0);
            const longlong2 vr0 = pr[0];
            const longlong2 vr1 = pr[1];
            r[0] = (int)vr0.x; r[1] = (int)vr0.y; r[2] = (int)vr1.x; r[3] = (int)vr1.y;
            const longlong2* pc = (const longlong2*)((const long long*)edges + (long long)E + e0);
            const longlong2 vc0 = pc[0];
            const longlong2 vc1 = pc[1];
            c[0] = (int)vc0.x; c[1] = (int)vc0.y; c[2] = (int)vc1.x; c[3] = (int)vc1.y;
        } else {
            const int4 vr = *(const int4*)((const int*)edges + e0);
            r[0] = vr.x; r[1] = vr.y; r[2] = vr.z; r[3] = vr.w;
            const int4 vc = *(const int4*)((const int*)edges + (long long)E + e0);
            c[0] = vc.x; c[1] = vc.y; c[2] = vc.z; c[3] = vc.w;
        }
        cnt = 4;
    } else {
        cnt = E - e0; if (cnt > 4) cnt = 4;
        for (int j = 0; j < cnt; j++) {
            r[j] = e64 ? (int)((const long long*)edges)[e0 + j]
                       : ((const int*)edges)[e0 + j];
            c[j] = e64 ? (int)((const long long*)edges)[(long long)E + e0 + j]
                       : ((const int*)edges)[(long long)E + e0 + j];
        }
    }
    #pragma unroll
    for (int j = 0; j < 4; j++) {
        if (j < cnt && (unsigned)c[j] < (unsigned)N && (unsigned)r[j] < (unsigned)N) {
            int pos = atomicAdd(&g_cur[c[j]], 1);
            if (pos < MAX_E) g_src[pos] = r[j];
        }
    }
}

// join: warp-per-node gather with fp16 tree reduction over 4-neighbor groups.
__global__ void __launch_bounds__(256) k_aggr(float* __restrict__ out,
                                              const float* __restrict__ bias, int N)
{
    const int gt   = blockIdx.x * blockDim.x + threadIdx.x;
    const int node = gt >> 5;
    const int lane = gt & 31;
    if (node >= N) return;

    const int start = g_rowptr[node];
    const int end   = g_rowptr[node + 1];

    float a0, a1, a2, a3;
    {
        const uint2 u = ((const uint2*)(g_bufh + (size_t)node * 64))[lane];
        const float2 f0 = __half22float2(u32_as_h2(u.x));
        const float2 f1 = __half22float2(u32_as_h2(u.y));
        a0 = f0.x; a1 = f0.y; a2 = f1.x; a3 = f1.y;
    }

    int k = start;
    for (; k + 4 <= end; k += 4) {
        const int j0 = g_src[k], j1 = g_src[k + 1], j2 = g_src[k + 2], j3 = g_src[k + 3];
        const uint2 u0 = ((const uint2*)(g_bufh + (size_t)j0 * 64))[lane];
        const uint2 u1 = ((const uint2*)(g_bufh + (size_t)j1 * 64))[lane];
        const uint2 u2 = ((const uint2*)(g_bufh + (size_t)j2 * 64))[lane];
        const uint2 u3 = ((const uint2*)(g_bufh + (size_t)j3 * 64))[lane];
        const __half2 sx = __hadd2(__hadd2(u32_as_h2(u0.x), u32_as_h2(u1.x)),
                                   __hadd2(u32_as_h2(u2.x), u32_as_h2(u3.x)));
        const __half2 sy = __hadd2(__hadd2(u32_as_h2(u0.y), u32_as_h2(u1.y)),
                                   __hadd2(u32_as_h2(u2.y), u32_as_h2(u3.y)));
        const float2 f0 = __half22float2(sx);
        const float2 f1 = __half22float2(sy);
        a0 += f0.x; a1 += f0.y; a2 += f1.x; a3 += f1.y;
    }
    for (; k < end; k++) {
        const int j = g_src[k];
        const uint2 u = ((const uint2*)(g_bufh + (size_t)j * 64))[lane];
        float2 f;
        f = __half22float2(u32_as_h2(u.x)); a0 += f.x; a1 += f.y;
        f = __half22float2(u32_as_h2(u.y)); a2 += f.x; a3 += f.y;
    }

    const float dvi = g_dinv[node];
    const float4 b = ((const float4*)bias)[lane];
    float4 r;
    r.x = a0 * dvi + b.x;
    r.y = a1 * dvi + b.y;
    r.z = a2 * dvi + b.z;
    r.w = a3 * dvi + b.w;
    ((float4*)(out + (size_t)node * D))[lane] = r;
}

// ---------------------------------------------------------------------------
extern "C" void kernel_launch(void* const* d_in, const int* in_sizes, int n_in,
                              void* d_out, int out_size)
{
    const float* x     = (const float*)d_in[0];
    const void*  edges = (const void*)d_in[1];
    const float* gamma = (const float*)d_in[2];
    const float* beta  = (const float*)d_in[3];
    const float* W     = (const float*)d_in[4];
    const float* bias  = (const float*)d_in[5];
    float*       out   = (float*)d_out;

    const int N = in_sizes[0] / D;
    const int E = in_sizes[1] / 2;
    const int nblk = (N + SCAN_B - 1) / SCAN_B;
    const int quartE = (E + 3) / 4;

    static cudaStream_t s1 = nullptr;
    static cudaEvent_t  evFork = nullptr, evJoin = nullptr;
    if (!s1) {
        cudaFuncSetAttribute(fused_ln_gemm_kernel,
                             cudaFuncAttributeMaxDynamicSharedMemorySize,
                             GEMM_SMEM_BYTES);
        cudaStreamCreateWithFlags(&s1, cudaStreamNonBlocking);
        cudaEventCreateWithFlags(&evFork, cudaEventDisableTiming);
        cudaEventCreateWithFlags(&evJoin, cudaEventDisableTiming);
    }

    // serial prefix on stream 0: init (+W convert, +status clear) -> hist
    k_init<<<(N + 255) / 256, 256>>>(edges, W, N, N);
    k_hist<<<(quartE + 255) / 256, 256>>>(edges, E, N);

    // fork after hist: GEMM (dinv from g_cnt in epilogue) on s1,
    // fused lookback scan -> fill on stream 0.
    cudaEventRecord(evFork, 0);
    cudaStreamWaitEvent(s1, evFork, 0);
    fused_ln_gemm_kernel<<<(N + 127) / 128, 512, GEMM_SMEM_BYTES, s1>>>(x, gamma, beta, N);
    cudaEventRecord(evJoin, s1);

    k_scan<<<nblk, SCAN_B>>>(N, E);
    k_fill<<<(quartE + 255) / 256, 256>>>(edges, E, N);

    // join and aggregate
    cudaStreamWaitEvent(0, evJoin, 0);
    k_aggr<<<(N * 32 + 255) / 256, 256>>>(out, bias, N);
}

// round 17
// speedup vs baseline: 1.0435x; 1.0435x over previous
#include <cuda_runtime.h>
#include <cuda_fp16.h>
#include <cstdint>

#define MAX_N   131072
#define MAX_E   1700000
#define D       128
#define SCAN_B  512
#define MAX_BLK 256   // MAX_N / SCAN_B

#define A_STRIDE 136
#define W_STRIDE 136
#define GEMM_SMEM_BYTES ((128 * A_STRIDE + 128 * W_STRIDE) * 2)

// ---- scratch (__device__ globals; no allocations allowed) ----
__device__ __align__(16) __half2 g_bufh[(size_t)MAX_N * 64];  // g = dinv*relu(LN(x))@W, fp16
__device__ __align__(16) __half2 g_Wh2[64 * 128];             // W in fp16, row-major [k][n]
__device__ float g_dinv[MAX_N];
__device__ int   g_cnt[MAX_N];
__device__ int   g_rowptr[MAX_N + 1];
__device__ int   g_cur[MAX_N];
__device__ int   g_blk[MAX_BLK];
__device__ int   g_src[MAX_E];
__device__ int   g_e64;
__device__ int   g_tick;

// ---------------------------------------------------------------------------
__device__ __forceinline__ unsigned h2_as_u32(__half2 h) {
    union { __half2 h; unsigned u; } cvt; cvt.h = h; return cvt.u;
}
__device__ __forceinline__ __half2 u32_as_h2(unsigned u) {
    union { unsigned u; __half2 h; } cvt; cvt.u = u; return cvt.h;
}
__device__ __forceinline__ uint32_t smem_u32(const void* p) {
    return (uint32_t)__cvta_generic_to_shared(p);
}

// ---------------------------------------------------------------------------
// k_init: zero g_cnt + dtype probe (block 0) + W->fp16 (blocks 1..32) + ticket.
__global__ void k_init(const void* __restrict__ edges, const float* __restrict__ W,
                       int N, int n) {
    __shared__ int bad;
    const int i = blockIdx.x * blockDim.x + threadIdx.x;
    if (i < n) g_cnt[i] = 0;
    if (blockIdx.x == 0) {
        if (threadIdx.x == 0) { bad = 0; g_tick = 0; }
        __syncthreads();
        if (threadIdx.x < 64) {
            long long v = ((const long long*)edges)[threadIdx.x];
            if (v < 0 || v >= (long long)N) atomicOr(&bad, 1);
        }
        __syncthreads();
        if (threadIdx.x == 0) g_e64 = bad ? 0 : 1;
    } else if (blockIdx.x <= 32) {
        const int j = (blockIdx.x - 1) * 256 + threadIdx.x;  // [0, 8192)
        const float2 w = ((const float2*)W)[j];
        g_Wh2[j] = __floats2half2_rn(w.x, w.y);
    }
}

// histogram over edge targets, 4 edges/thread (vector fast path when E%4==0).
__global__ void k_hist(const void* __restrict__ edges, int E, int N) {
    const int t  = blockIdx.x * blockDim.x + threadIdx.x;
    const int e0 = t * 4;
    if (e0 >= E) return;
    const int e64 = g_e64;
    int c[4];
    int cnt;
    if (e0 + 4 <= E && ((E & 3) == 0)) {
        if (e64) {
            const longlong2* p = (const longlong2*)((const long long*)edges + (long long)E + e0);
            const longlong2 v0 = p[0];
            const longlong2 v1 = p[1];
            c[0] = (int)v0.x; c[1] = (int)v0.y; c[2] = (int)v1.x; c[3] = (int)v1.y;
        } else {
            const int4 v = *(const int4*)((const int*)edges + (long long)E + e0);
            c[0] = v.x; c[1] = v.y; c[2] = v.z; c[3] = v.w;
        }
        cnt = 4;
    } else {
        cnt = E - e0; if (cnt > 4) cnt = 4;
        for (int j = 0; j < cnt; j++)
            c[j] = e64 ? (int)((const long long*)edges)[(long long)E + e0 + j]
                       : ((const int*)edges)[(long long)E + e0 + j];
    }
    #pragma unroll
    for (int j = 0; j < 4; j++)
        if (j < cnt && (unsigned)c[j] < (unsigned)N) atomicAdd(&g_cnt[c[j]], 1);
}

// per-block scan + dinv; last block scans block totals (ticket pattern).
__global__ void k_scan1(int n, int nblk) {
    __shared__ int s[SCAN_B];
    __shared__ int isLast;
    const int tid = threadIdx.x;
    const int i   = blockIdx.x * SCAN_B + tid;
    const int v   = (i < n) ? g_cnt[i] : 0;
    if (i < n) g_dinv[i] = rsqrtf((float)(v + 1));
    s[tid] = v;
    __syncthreads();
    #pragma unroll
    for (int off = 1; off < SCAN_B; off <<= 1) {
        int t = (tid >= off) ? s[tid - off] : 0;
        __syncthreads();
        s[tid] += t;
        __syncthreads();
    }
    if (i < n) g_rowptr[i] = s[tid] - v;
    if (tid == SCAN_B - 1) g_blk[blockIdx.x] = s[tid];

    __threadfence();
    if (tid == 0) isLast = (atomicAdd(&g_tick, 1) == nblk - 1) ? 1 : 0;
    __syncthreads();
    if (isLast) {
        const int bv = (tid < nblk) ? g_blk[tid] : 0;
        s[tid] = (tid < MAX_BLK) ? bv : 0;
        __syncthreads();
        #pragma unroll
        for (int off = 1; off < MAX_BLK; off <<= 1) {
            int t = (tid >= off && tid < MAX_BLK) ? s[tid - off] : 0;
            __syncthreads();
            if (tid < MAX_BLK) s[tid] += t;
            __syncthreads();
        }
        if (tid < nblk) g_blk[tid] = s[tid] - bv;
    }
}

// add block offsets; init cursors; set rowptr[N]
__global__ void k_scan3(int n, int E) {
    const int i = blockIdx.x * SCAN_B + threadIdx.x;
    if (i < n) {
        int r = g_rowptr[i] + g_blk[blockIdx.x];
        g_rowptr[i] = r;
        g_cur[i]    = r;
    }
    if (blockIdx.x == 0 && threadIdx.x == 0) g_rowptr[n] = E;
}

// ---------------------------------------------------------------------------
// Fused LayerNorm -> ReLU -> HMMA GEMM -> *rsqrt(cnt+1), fp16 out.
// Stream-1 branch; depends only on k_init (W) + k_hist (g_cnt).
__global__ void __launch_bounds__(512) fused_ln_gemm_kernel(
    const float* __restrict__ x,
    const float* __restrict__ gamma,
    const float* __restrict__ beta,
    int N)
{
    extern __shared__ __align__(16) __half smem[];
    __half* A_s = smem;                     // [128][A_STRIDE]
    __half* W_s = smem + 128 * A_STRIDE;    // [128][W_STRIDE]

    const int tid  = threadIdx.x;
    const int warp = tid >> 5;
    const int lane = tid & 31;
    const int node0 = blockIdx.x * 128;

    {
        const uint4* src = (const uint4*)g_Wh2;
        #pragma unroll
        for (int i = tid; i < 2048; i += 512) {
            const int row = i >> 4;
            const int c8  = i & 15;
            *(uint4*)&W_s[row * W_STRIDE + c8 * 8] = src[i];
        }
    }

    #pragma unroll
    for (int rr = 0; rr < 8; rr++) {
        const int n = warp * 8 + rr;
        const int node = node0 + n;
        float v0 = 0.f, v1 = 0.f, v2 = 0.f, v3 = 0.f;
        if (node < N) {
            const float* xr = x + (size_t)node * D;
            v0 = xr[lane]; v1 = xr[lane + 32]; v2 = xr[lane + 64]; v3 = xr[lane + 96];
        }
        float s  = v0 + v1 + v2 + v3;
        float sq = v0 * v0 + v1 * v1 + v2 * v2 + v3 * v3;
        #pragma unroll
        for (int off = 16; off; off >>= 1) {
            s  += __shfl_xor_sync(0xFFFFFFFFu, s,  off);
            sq += __shfl_xor_sync(0xFFFFFFFFu, sq, off);
        }
        const float mu  = s * (1.0f / 128.0f);
        const float var = sq * (1.0f / 128.0f) - mu * mu;
        const float rs  = rsqrtf(var + 1e-5f);
        __half* ar = &A_s[n * A_STRIDE];
        ar[lane]      = __float2half(fmaxf((v0 - mu) * rs * gamma[lane]      + beta[lane],      0.f));
        ar[lane + 32] = __float2half(fmaxf((v1 - mu) * rs * gamma[lane + 32] + beta[lane + 32], 0.f));
        ar[lane + 64] = __float2half(fmaxf((v2 - mu) * rs * gamma[lane + 64] + beta[lane + 64], 0.f));
        ar[lane + 96] = __float2half(fmaxf((v3 - mu) * rs * gamma[lane + 96] + beta[lane + 96], 0.f));
    }
    __syncthreads();

    const int wm = warp >> 2;
    const int wn = warp & 3;

    float acc[2][4][4];
    #pragma unroll
    for (int mt = 0; mt < 2; mt++)
        #pragma unroll
        for (int nn = 0; nn < 4; nn++)
            #pragma unroll
            for (int c = 0; c < 4; c++) acc[mt][nn][c] = 0.f;

    const uint32_t a_addr0 = smem_u32(&A_s[(wm * 32 + (lane & 15)) * A_STRIDE + (lane >> 4) * 8]);
    const uint32_t a_addr1 = a_addr0 + 16 * A_STRIDE * 2;
    const uint32_t b_addr0 = smem_u32(&W_s[(lane & 15) * W_STRIDE + wn * 32]);

    #pragma unroll
    for (int kk = 0; kk < 8; kk++) {
        uint32_t b0[4], b1[4];
        const uint32_t b_k = b_addr0 + kk * (16 * W_STRIDE * 2);
        #pragma unroll
        for (int nn = 0; nn < 4; nn++) {
            asm volatile("ldmatrix.sync.aligned.m8n8.x2.trans.shared.b16 {%0,%1}, [%2];"
                         : "=r"(b0[nn]), "=r"(b1[nn])
                         : "r"(b_k + nn * 16));
        }
        uint32_t a[2][4];
        asm volatile("ldmatrix.sync.aligned.m8n8.x4.shared.b16 {%0,%1,%2,%3}, [%4];"
                     : "=r"(a[0][0]), "=r"(a[0][1]), "=r"(a[0][2]), "=r"(a[0][3])
                     : "r"(a_addr0 + kk * 32));
        asm volatile("ldmatrix.sync.aligned.m8n8.x4.shared.b16 {%0,%1,%2,%3}, [%4];"
                     : "=r"(a[1][0]), "=r"(a[1][1]), "=r"(a[1][2]), "=r"(a[1][3])
                     : "r"(a_addr1 + kk * 32));
        #pragma unroll
        for (int mt = 0; mt < 2; mt++)
            #pragma unroll
            for (int nn = 0; nn < 4; nn++)
                asm volatile("mma.sync.aligned.m16n8k16.row.col.f32.f16.f16.f32 "
                             "{%0,%1,%2,%3}, {%4,%5,%6,%7}, {%8,%9}, {%0,%1,%2,%3};"
                             : "+f"(acc[mt][nn][0]), "+f"(acc[mt][nn][1]),
                               "+f"(acc[mt][nn][2]), "+f"(acc[mt][nn][3])
                             : "r"(a[mt][0]), "r"(a[mt][1]), "r"(a[mt][2]), "r"(a[mt][3]),
                               "r"(b0[nn]), "r"(b1[nn]));
    }

    const int group = lane >> 2;
    const int qp    = lane & 3;
    #pragma unroll
    for (int mt = 0; mt < 2; mt++) {
        const int r0 = node0 + wm * 32 + mt * 16 + group;
        const int r1 = r0 + 8;
        const float dv0 = (r0 < N) ? rsqrtf((float)(g_cnt[r0] + 1)) : 0.f;
        const float dv1 = (r1 < N) ? rsqrtf((float)(g_cnt[r1] + 1)) : 0.f;
        #pragma unroll
        for (int nn = 0; nn < 4; nn++) {
            const int col2 = wn * 16 + nn * 4 + qp;
            if (r0 < N)
                g_bufh[(size_t)r0 * 64 + col2] =
                    __floats2half2_rn(acc[mt][nn][0] * dv0, acc[mt][nn][1] * dv0);
            if (r1 < N)
                g_bufh[(size_t)r1 * 64 + col2] =
                    __floats2half2_rn(acc[mt][nn][2] * dv1, acc[mt][nn][3] * dv1);
        }
    }
}

// ---------------------------------------------------------------------------
// CSR fill, 4 edges/thread.
__global__ void k_fill(const void* __restrict__ edges, int E, int N) {
    const int t  = blockIdx.x * blockDim.x + threadIdx.x;
    const int e0 = t * 4;
    if (e0 >= E) return;
    const int e64 = g_e64;
    int r[4], c[4];
    int cnt;
    if (e0 + 4 <= E && ((E & 3) == 0)) {
        if (e64) {
            const longlong2* pr = (const longlong2*)((const long long*)edges + e0);
            const longlong2 vr0 = pr[0];
            const longlong2 vr1 = pr[1];
            r[0] = (int)vr0.x; r[1] = (int)vr0.y; r[2] = (int)vr1.x; r[3] = (int)vr1.y;
            const longlong2* pc = (const longlong2*)((const long long*)edges + (long long)E + e0);
            const longlong2 vc0 = pc[0];
            const longlong2 vc1 = pc[1];
            c[0] = (int)vc0.x; c[1] = (int)vc0.y; c[2] = (int)vc1.x; c[3] = (int)vc1.y;
        } else {
            const int4 vr = *(const int4*)((const int*)edges + e0);
            r[0] = vr.x; r[1] = vr.y; r[2] = vr.z; r[3] = vr.w;
            const int4 vc = *(const int4*)((const int*)edges + (long long)E + e0);
            c[0] = vc.x; c[1] = vc.y; c[2] = vc.z; c[3] = vc.w;
        }
        cnt = 4;
    } else {
        cnt = E - e0; if (cnt > 4) cnt = 4;
        for (int j = 0; j < cnt; j++) {
            r[j] = e64 ? (int)((const long long*)edges)[e0 + j]
                       : ((const int*)edges)[e0 + j];
            c[j] = e64 ? (int)((const long long*)edges)[(long long)E + e0 + j]
                       : ((const int*)edges)[(long long)E + e0 + j];
        }
    }
    #pragma unroll
    for (int j = 0; j < 4; j++) {
        if (j < cnt && (unsigned)c[j] < (unsigned)N && (unsigned)r[j] < (unsigned)N) {
            int pos = atomicAdd(&g_cur[c[j]], 1);
            if (pos < MAX_E) g_src[pos] = r[j];
        }
    }
}

// join: warp-per-node gather with fp16 tree reduction over 4-neighbor groups.
__global__ void __launch_bounds__(256) k_aggr(float* __restrict__ out,
                                              const float* __restrict__ bias, int N)
{
    const int gt   = blockIdx.x * blockDim.x + threadIdx.x;
    const int node = gt >> 5;
    const int lane = gt & 31;
    if (node >= N) return;

    const int start = g_rowptr[node];
    const int end   = g_rowptr[node + 1];

    float a0, a1, a2, a3;
    {
        const uint2 u = ((const uint2*)(g_bufh + (size_t)node * 64))[lane];
        const float2 f0 = __half22float2(u32_as_h2(u.x));
        const float2 f1 = __half22float2(u32_as_h2(u.y));
        a0 = f0.x; a1 = f0.y; a2 = f1.x; a3 = f1.y;
    }

    int k = start;
    for (; k + 4 <= end; k += 4) {
        const int j0 = g_src[k], j1 = g_src[k + 1], j2 = g_src[k + 2], j3 = g_src[k + 3];
        const uint2 u0 = ((const uint2*)(g_bufh + (size_t)j0 * 64))[lane];
        const uint2 u1 = ((const uint2*)(g_bufh + (size_t)j1 * 64))[lane];
        const uint2 u2 = ((const uint2*)(g_bufh + (size_t)j2 * 64))[lane];
        const uint2 u3 = ((const uint2*)(g_bufh + (size_t)j3 * 64))[lane];
        const __half2 sx = __hadd2(__hadd2(u32_as_h2(u0.x), u32_as_h2(u1.x)),
                                   __hadd2(u32_as_h2(u2.x), u32_as_h2(u3.x)));
        const __half2 sy = __hadd2(__hadd2(u32_as_h2(u0.y), u32_as_h2(u1.y)),
                                   __hadd2(u32_as_h2(u2.y), u32_as_h2(u3.y)));
        const float2 f0 = __half22float2(sx);
        const float2 f1 = __half22float2(sy);
        a0 += f0.x; a1 += f0.y; a2 += f1.x; a3 += f1.y;
    }
    for (; k < end; k++) {
        const int j = g_src[k];
        const uint2 u = ((const uint2*)(g_bufh + (size_t)j * 64))[lane];
        float2 f;
        f = __half22float2(u32_as_h2(u.x)); a0 += f.x; a1 += f.y;
        f = __half22float2(u32_as_h2(u.y)); a2 += f.x; a3 += f.y;
    }

    const float dvi = g_dinv[node];
    const float4 b = ((const float4*)bias)[lane];
    float4 r;
    r.x = a0 * dvi + b.x;
    r.y = a1 * dvi + b.y;
    r.z = a2 * dvi + b.z;
    r.w = a3 * dvi + b.w;
    ((float4*)(out + (size_t)node * D))[lane] = r;
}

// ---------------------------------------------------------------------------
extern "C" void kernel_launch(void* const* d_in, const int* in_sizes, int n_in,
                              void* d_out, int out_size)
{
    const float* x     = (const float*)d_in[0];
    const void*  edges = (const void*)d_in[1];
    const float* gamma = (const float*)d_in[2];
    const float* beta  = (const float*)d_in[3];
    const float* W     = (const float*)d_in[4];
    const float* bias  = (const float*)d_in[5];
    float*       out   = (float*)d_out;

    const int N = in_sizes[0] / D;
    const int E = in_sizes[1] / 2;
    const int nblk = (N + SCAN_B - 1) / SCAN_B;
    const int quartE = (E + 3) / 4;

    static cudaStream_t s1 = nullptr;
    static cudaEvent_t  evFork = nullptr, evJoin = nullptr;
    if (!s1) {
        cudaFuncSetAttribute(fused_ln_gemm_kernel,
                             cudaFuncAttributeMaxDynamicSharedMemorySize,
                             GEMM_SMEM_BYTES);
        cudaStreamCreateWithFlags(&s1, cudaStreamNonBlocking);
        cudaEventCreateWithFlags(&evFork, cudaEventDisableTiming);
        cudaEventCreateWithFlags(&evJoin, cudaEventDisableTiming);
    }

    // serial prefix on stream 0: init (+W convert) -> hist
    k_init<<<(N + 255) / 256, 256>>>(edges, W, N, N);
    k_hist<<<(quartE + 255) / 256, 256>>>(edges, E, N);

    // fork after hist: GEMM (dinv from g_cnt in epilogue) on s1,
    // scan1 -> scan3 -> fill on stream 0.
    cudaEventRecord(evFork, 0);
    cudaStreamWaitEvent(s1, evFork, 0);
    fused_ln_gemm_kernel<<<(N + 127) / 128, 512, GEMM_SMEM_BYTES, s1>>>(x, gamma, beta, N);
    cudaEventRecord(evJoin, s1);

    k_scan1<<<nblk, SCAN_B>>>(N, nblk);
    k_scan3<<<nblk, SCAN_B>>>(N, E);
    k_fill<<<(quartE + 255) / 256, 256>>>(edges, E, N);

    // join and aggregate
    cudaStreamWaitEvent(0, evJoin, 0);
    k_aggr<<<(N * 32 + 255) / 256, 256>>>(out, bias, N);
}